// round 5
// baseline (speedup 1.0000x reference)
#include <cuda_runtime.h>

#define T_LEN   16384
#define NUMB    64
#define KTAPS   129
#define TILE_T  128
#define BPB     8       // bands per block (1 per warp)
#define THREADS 256
#define NGROUPS (NUMB / BPB)

// Device scratch (allocation-free): packed RBF params + partial sums.
// Pr[b*64+c] = { -sigma_r*L, 2*sigma_r*L*c_r, -sigma_r*L*c_r^2, fc_r }
__device__ float4 g_Pr[NUMB * NUMB];
__device__ float4 g_Pi[NUMB * NUMB];
__device__ float2 g_part[NGROUPS][T_LEN];   // per band-group partial (yr, yi)

__global__ void precompute_kernel(const float* __restrict__ cr, const float* __restrict__ ci,
                                  const float* __restrict__ sr, const float* __restrict__ si,
                                  const float* __restrict__ fr, const float* __restrict__ fi)
{
    int idx = blockIdx.x * blockDim.x + threadIdx.x;
    if (idx >= NUMB * NUMB) return;
    const float L = 1.4426950408889634f;  // log2(e)
    float s = sr[idx] * L;
    float c = cr[idx];
    g_Pr[idx] = make_float4(-s, 2.0f * s * c, -s * c * c, fr[idx]);
    s = si[idx] * L;
    c = ci[idx];
    g_Pi[idx] = make_float4(-s, 2.0f * s * c, -s * c * c, fi[idx]);
}

__device__ __forceinline__ float ex2f(float x) {
    float r; asm("ex2.approx.ftz.f32 %0, %1;" : "=f"(r) : "f"(x)); return r;
}
__device__ __forceinline__ float sqrtaf(float x) {
    float r; asm("sqrt.approx.f32 %0, %1;" : "=f"(r) : "f"(x)); return r;
}

__global__ __launch_bounds__(THREADS)
void fused_kernel(const float* __restrict__ xr, const float* __restrict__ xi,
                  const float* __restrict__ w1r, const float* __restrict__ w1i,
                  const float* __restrict__ w3r, const float* __restrict__ w3i)
{
    __shared__ __align__(16) float  sxr[TILE_T + 128];      // tile + 64 halo each side
    __shared__ __align__(16) float  sxi[TILE_T + 128];
    __shared__ __align__(16) float2 swp[BPB][130];          // interleaved (wr,wi), padded
    __shared__ __align__(16) float4 sPr[BPB][NUMB];
    __shared__ __align__(16) float4 sPi[BPB][NUMB];
    __shared__ float2 sred[BPB][TILE_T];

    const int tid  = threadIdx.x;
    const int wb   = tid >> 5;        // local band (warp)
    const int lane = tid & 31;
    const int tileBase = blockIdx.x * TILE_T;
    const int band = blockIdx.y * BPB + wb;

    // ---- stage smem ----
    for (int i = tid; i < TILE_T + 128; i += THREADS) {
        int t = tileBase - 64 + i;
        bool ok = (t >= 0) && (t < T_LEN);
        sxr[i] = ok ? xr[t] : 0.0f;
        sxi[i] = ok ? xi[t] : 0.0f;
    }
    for (int i = tid; i < BPB * KTAPS; i += THREADS) {
        int bb = i / KTAPS, k = i - bb * KTAPS;
        int gb = blockIdx.y * BPB + bb;
        swp[bb][k] = make_float2(w1r[gb * KTAPS + k], w1i[gb * KTAPS + k]);
    }
    for (int i = tid; i < BPB * NUMB; i += THREADS) {
        int bb = i >> 6, c = i & 63;
        int gb = blockIdx.y * BPB + bb;
        sPr[bb][c] = g_Pr[gb * NUMB + c];
        sPi[bb][c] = g_Pi[gb * NUMB + c];
    }
    __syncthreads();

    // ---- complex conv: 4 consecutive t per lane, sliding float4 window ----
    float x1r[4] = {0.f, 0.f, 0.f, 0.f};
    float x1i[4] = {0.f, 0.f, 0.f, 0.f};
    const float4* xr4 = (const float4*)sxr;
    const float4* xi4 = (const float4*)sxi;

    float4 Ar = xr4[lane];
    float4 Ai = xi4[lane];
    #pragma unroll
    for (int kg = 0; kg < 32; kg++) {
        float4 Br = xr4[lane + kg + 1];
        float4 Bi = xi4[lane + kg + 1];
        float4 wA = *(const float4*)&swp[wb][4 * kg];
        float4 wB = *(const float4*)&swp[wb][4 * kg + 2];
        float axr[8] = {Ar.x, Ar.y, Ar.z, Ar.w, Br.x, Br.y, Br.z, Br.w};
        float axi[8] = {Ai.x, Ai.y, Ai.z, Ai.w, Bi.x, Bi.y, Bi.z, Bi.w};
        float wr[4] = {wA.x, wA.z, wB.x, wB.z};
        float wi[4] = {wA.y, wA.w, wB.y, wB.w};
        #pragma unroll
        for (int kk = 0; kk < 4; kk++) {
            #pragma unroll
            for (int j = 0; j < 4; j++) {
                float xv = axr[kk + j], yv = axi[kk + j];
                x1r[j] = fmaf(xv,  wr[kk], x1r[j]);
                x1r[j] = fmaf(-yv, wi[kk], x1r[j]);
                x1i[j] = fmaf(xv,  wi[kk], x1i[j]);
                x1i[j] = fmaf(yv,  wr[kk], x1i[j]);
            }
        }
        Ar = Br; Ai = Bi;
    }
    {   // tap k = 128
        float4 Cr = xr4[lane + 32];
        float4 Ci = xi4[lane + 32];
        float2 wl = swp[wb][128];
        float cR[4] = {Cr.x, Cr.y, Cr.z, Cr.w};
        float cI[4] = {Ci.x, Ci.y, Ci.z, Ci.w};
        #pragma unroll
        for (int j = 0; j < 4; j++) {
            x1r[j] = fmaf(cR[j],  wl.x, x1r[j]);
            x1r[j] = fmaf(-cI[j], wl.y, x1r[j]);
            x1i[j] = fmaf(cR[j],  wl.y, x1i[j]);
            x1i[j] = fmaf(cI[j],  wl.x, x1i[j]);
        }
    }

    // ---- RBF mixture: exp2(m*s2 + a*u + v) ----
    float m[4], a[4], oR[4] = {0.f,0.f,0.f,0.f}, oI[4] = {0.f,0.f,0.f,0.f};
    #pragma unroll
    for (int j = 0; j < 4; j++) {
        m[j] = x1r[j] * x1r[j] + x1i[j] * x1i[j];
        a[j] = sqrtaf(m[j]);
    }
    #pragma unroll 4
    for (int c = 0; c < NUMB; c++) {
        float4 pr = sPr[wb][c];
        float4 pi = sPi[wb][c];
        #pragma unroll
        for (int j = 0; j < 4; j++) {
            float er = ex2f(fmaf(m[j], pr.x, fmaf(a[j], pr.y, pr.z)));
            oR[j] = fmaf(er, pr.w, oR[j]);
            float ei = ex2f(fmaf(m[j], pi.x, fmaf(a[j], pi.y, pi.z)));
            oI[j] = fmaf(ei, pi.w, oI[j]);
        }
    }

    // ---- combine + band weight ----
    float w3rb = __ldg(&w3r[band]);
    float w3ib = __ldg(&w3i[band]);
    #pragma unroll
    for (int j = 0; j < 4; j++) {
        float q   = oR[j] + 1.0f;
        float x2r = q * x1r[j] - oI[j] * x1i[j];
        float x2i = q * x1i[j] + oI[j] * x1r[j];
        float yr = x2r * w3rb - x2i * w3ib;
        float yi = x2r * w3ib + x2i * w3rb;
        sred[wb][4 * lane + j] = make_float2(yr, yi);
    }
    __syncthreads();

    // ---- reduce 8 bands within block, write partial for this band group ----
    if (tid < TILE_T) {
        float r = 0.f, im = 0.f;
        #pragma unroll
        for (int w = 0; w < BPB; w++) {
            float2 v = sred[w][tid];
            r += v.x; im += v.y;
        }
        g_part[blockIdx.y][tileBase + tid] = make_float2(r, im);
    }
}

// layout = 0: REAL PART ONLY, float32[T]  (complex ref cast to float32 drops imag)
// layout = 1: planar float32[2*T]  [real block | imag block]
// layout = 2: interleaved complex64
__global__ __launch_bounds__(256)
void reduce_kernel(float* __restrict__ out, int layout)
{
    int t = blockIdx.x * blockDim.x + threadIdx.x;
    if (t >= T_LEN) return;
    float r = 0.f, im = 0.f;
    #pragma unroll
    for (int g = 0; g < NGROUPS; g++) {
        float2 v = g_part[g][t];
        r += v.x; im += v.y;
    }
    if (layout == 0) {
        out[t] = r;
    } else if (layout == 1) {
        out[t]         = r;
        out[T_LEN + t] = im;
    } else {
        out[2 * t]     = r;
        out[2 * t + 1] = im;
    }
}

extern "C" void kernel_launch(void* const* d_in, const int* in_sizes, int n_in,
                              void* d_out, int out_size)
{
    // Input ordering: order A (dict/signature) confirmed by in_sizes[0]==16384.
    int I_xr, I_xi, I_w1r, I_w1i, I_cr, I_ci, I_sr, I_si, I_fcr, I_fci, I_w3r, I_w3i;
    if (in_sizes[0] == T_LEN) {
        I_xr = 0;  I_xi = 1;  I_w1r = 2; I_w1i = 3; I_cr = 4;  I_ci = 5;
        I_sr = 6;  I_si = 7;  I_fcr = 8; I_fci = 9; I_w3r = 10; I_w3i = 11;
    } else {
        I_ci = 0;  I_cr = 1;  I_fci = 2; I_fcr = 3; I_si = 4;  I_sr = 5;
        I_w1i = 6; I_w1r = 7; I_w3i = 8; I_w3r = 9; I_xi = 10; I_xr = 11;
    }

    const float* x_r  = (const float*)d_in[I_xr];
    const float* x_i  = (const float*)d_in[I_xi];
    const float* w1_r = (const float*)d_in[I_w1r];
    const float* w1_i = (const float*)d_in[I_w1i];
    const float* c_r  = (const float*)d_in[I_cr];
    const float* c_i  = (const float*)d_in[I_ci];
    const float* s_r  = (const float*)d_in[I_sr];
    const float* s_i  = (const float*)d_in[I_si];
    const float* fc_r = (const float*)d_in[I_fcr];
    const float* fc_i = (const float*)d_in[I_fci];
    const float* w3_r = (const float*)d_in[I_w3r];
    const float* w3_i = (const float*)d_in[I_w3i];
    float* out = (float*)d_out;

    // Output format: out_size==16384 observed (R2-R4 deduction) and complex64 is
    // not a harness dtype -> float32[16384] = real(y3) (astype drops imag).
    int layout;
    if (out_size == T_LEN)          layout = 0;  // real part only
    else if (out_size == 2 * T_LEN) layout = 1;  // planar float32
    else                            layout = 2;  // interleaved complex

    precompute_kernel<<<(NUMB * NUMB + 255) / 256, 256>>>(c_r, c_i, s_r, s_i, fc_r, fc_i);

    dim3 grid(T_LEN / TILE_T, NGROUPS);
    fused_kernel<<<grid, THREADS>>>(x_r, x_i, w1_r, w1_i, w3_r, w3_i);

    reduce_kernel<<<T_LEN / 256, 256>>>(out, layout);
}